// round 8
// baseline (speedup 1.0000x reference)
#include <cuda_runtime.h>
#include <cuda_bf16.h>
#include <cstdint>
#include <math.h>

// ============================================================================
// StandardAttention, B=4, S=2048, D=2048, H=16, Dh=128, fp32.
// R8: bf16x3 GEMM with PRE-SPLIT hi/lo bf16x2 planes in gmem (split kernels),
//     removing all cvt/sub ALU from the GEMM inner loop (R7 bottleneck).
//     Inner loop = LDS.32 x2 + HMMA only. Numerics identical to R7.
// Attention: SIMT flash kernel (unchanged from R7).
// ============================================================================

#define D_MODEL 2048
#define SEQ     2048
#define BATCH   4
#define NHEADS  16
#define DHEAD   128
#define MROWS   (BATCH * SEQ)          // 8192

__device__ float    g_Q  [ (size_t)MROWS * D_MODEL ];
__device__ float    g_K  [ (size_t)MROWS * D_MODEL ];
__device__ float    g_V  [ (size_t)MROWS * D_MODEL ];
__device__ float    g_AO [ (size_t)MROWS * D_MODEL ];
__device__ uint32_t g_Xhi[ (size_t)MROWS * D_MODEL / 2 ];   // 32MB
__device__ uint32_t g_Xlo[ (size_t)MROWS * D_MODEL / 2 ];
__device__ uint32_t g_Whi[ (size_t)D_MODEL * D_MODEL / 2 ]; // 8MB
__device__ uint32_t g_Wlo[ (size_t)D_MODEL * D_MODEL / 2 ];

// ---------------------------------------------------------------------------
// Helpers
// ---------------------------------------------------------------------------
__device__ __forceinline__ uint32_t smem_u32(const void* p) {
    uint32_t a;
    asm("{ .reg .u64 t; cvta.to.shared.u64 t, %1; cvt.u32.u64 %0, t; }"
        : "=r"(a) : "l"(p));
    return a;
}
__device__ __forceinline__ void cp_async16(uint32_t dst, const void* src) {
    asm volatile("cp.async.cg.shared.global [%0], [%1], 16;"
                 :: "r"(dst), "l"(src) : "memory");
}
__device__ __forceinline__ void cp_commit() {
    asm volatile("cp.async.commit_group;" ::: "memory");
}
template<int N> __device__ __forceinline__ void cp_wait() {
    asm volatile("cp.async.wait_group %0;" :: "n"(N) : "memory");
}

__device__ __forceinline__ void mma_bf16(float* d, const uint32_t* a,
                                         const uint32_t* b) {
    asm volatile(
        "mma.sync.aligned.m16n8k16.row.col.f32.bf16.bf16.f32 "
        "{%0,%1,%2,%3}, {%4,%5,%6,%7}, {%8,%9}, {%0,%1,%2,%3};"
        : "+f"(d[0]), "+f"(d[1]), "+f"(d[2]), "+f"(d[3])
        : "r"(a[0]), "r"(a[1]), "r"(a[2]), "r"(a[3]), "r"(b[0]), "r"(b[1]));
}

__device__ __forceinline__ void split2(float2 v, uint32_t& hi, uint32_t& lo) {
    asm("cvt.rn.bf16x2.f32 %0, %1, %2;" : "=r"(hi) : "f"(v.y), "f"(v.x));
    const float hx = __uint_as_float(hi << 16);
    const float hy = __uint_as_float(hi & 0xffff0000u);
    const float lx = v.x - hx;
    const float ly = v.y - hy;
    asm("cvt.rn.bf16x2.f32 %0, %1, %2;" : "=r"(lo) : "f"(ly), "f"(lx));
}

// ---------------------------------------------------------------------------
// Pre-split kernel: fp32 -> packed bf16x2 hi/lo planes. hi[i] holds rounded
// pair (e2i, e2i+1); lo[i] the rounded residuals. Bandwidth-bound.
// ---------------------------------------------------------------------------
__global__ void __launch_bounds__(256) split_kernel(
    const float* __restrict__ src, uint32_t* __restrict__ hi,
    uint32_t* __restrict__ lo, int n2)
{
    const int i = blockIdx.x * 256 + threadIdx.x;
    if (i < n2) {
        const float2 v = ((const float2*)src)[i];
        uint32_t h, l;
        split2(v, h, l);
        hi[i] = h;
        lo[i] = l;
    }
}

// ---------------------------------------------------------------------------
// Pre-split bf16x3 GEMM-NT: C[M,2048] = A * B^T, operands given as hi/lo
// bf16x2 planes ([row][k/2] uint32, row stride KW=1024).
// CTA 128x256, BK=32, 3-stage cp.async. 8 warps, warp tile 64x64.
// Plane row stride 20 uint32 -> LDS.32 bank = (20g+q) mod 32: conflict-free.
// ---------------------------------------------------------------------------
#define GBM 128
#define GBN 256
#define GBK 32
#define GSTAGES 3
#define NCHUNK (D_MODEL / GBK)          // 64
#define KW   (D_MODEL / 2)              // 1024 uint32 per gmem row
#define PSTR 20                         // smem plane row stride (uint32)
#define A_PL (GBM * PSTR)               // 2560
#define B_PL (GBN * PSTR)               // 5120
#define STAGE_U (2 * A_PL + 2 * B_PL)   // 15360 uint32
#define GEMM_SMEM_BYTES (GSTAGES * STAGE_U * 4)   // 184320

__global__ void __launch_bounds__(256, 1) gemm_pre(
    const uint32_t* __restrict__ Ahi, const uint32_t* __restrict__ Alo,
    const uint32_t* __restrict__ Bhi, const uint32_t* __restrict__ Blo,
    float* __restrict__ C)
{
    extern __shared__ uint32_t smu[];
    const int t  = threadIdx.x;
    const int w  = t >> 5;
    const int l  = t & 31;
    const int g  = l >> 2;
    const int q  = l & 3;
    const int wm = w >> 2;
    const int wn = w & 3;
    const int bm = blockIdx.y * GBM;
    const int bn = blockIdx.x * GBN;

    float acc[4][8][4];
#pragma unroll
    for (int mi = 0; mi < 4; mi++)
#pragma unroll
        for (int ni = 0; ni < 8; ni++)
#pragma unroll
            for (int c = 0; c < 4; c++) acc[mi][ni][c] = 0.0f;

    auto load_stage = [&](int s, int chunk) {
        uint32_t* sAh = smu + s * STAGE_U;
        uint32_t* sAl = sAh + A_PL;
        uint32_t* sBh = sAl + A_PL;
        uint32_t* sBl = sBh + B_PL;
        const int col0 = chunk * 16;           // uint32 col offset
#pragma unroll
        for (int i = 0; i < 2; i++) {          // A: 128 rows x 16 u32, 4 cp/row
            const int idx = i * 256 + t, r = idx >> 2, c = idx & 3;
            const size_t go = (size_t)(bm + r) * KW + col0 + c * 4;
            cp_async16(smem_u32(sAh + r * PSTR + c * 4), Ahi + go);
            cp_async16(smem_u32(sAl + r * PSTR + c * 4), Alo + go);
        }
#pragma unroll
        for (int i = 0; i < 4; i++) {          // B: 256 rows
            const int idx = i * 256 + t, r = idx >> 2, c = idx & 3;
            const size_t go = (size_t)(bn + r) * KW + col0 + c * 4;
            cp_async16(smem_u32(sBh + r * PSTR + c * 4), Bhi + go);
            cp_async16(smem_u32(sBl + r * PSTR + c * 4), Blo + go);
        }
    };

#pragma unroll
    for (int s = 0; s < GSTAGES - 1; s++) { load_stage(s, s); cp_commit(); }

    for (int c = 0; c < NCHUNK; c++) {
        __syncthreads();
        const int lc = c + GSTAGES - 1;
        if (lc < NCHUNK) load_stage(lc % GSTAGES, lc);
        cp_commit();
        cp_wait<GSTAGES - 2>();
        __syncthreads();

        const uint32_t* sAh = smu + (c % GSTAGES) * STAGE_U + (wm * 64) * PSTR;
        const uint32_t* sAl = sAh + A_PL;
        const uint32_t* sBh = smu + (c % GSTAGES) * STAGE_U + 2 * A_PL + (wn * 64) * PSTR;
        const uint32_t* sBl = sBh + B_PL;

#pragma unroll
        for (int ks = 0; ks < 2; ks++) {
            const int kb = ks * 8 + q;         // uint32 (k-pair) index

            uint32_t bhi[8][2], blo[8][2];
#pragma unroll
            for (int ni = 0; ni < 8; ni++) {
                const int nrow = (ni * 8 + g) * PSTR;
                bhi[ni][0] = sBh[nrow + kb];
                bhi[ni][1] = sBh[nrow + kb + 4];
                blo[ni][0] = sBl[nrow + kb];
                blo[ni][1] = sBl[nrow + kb + 4];
            }

#pragma unroll
            for (int mi = 0; mi < 4; mi++) {
                const int r0 = (mi * 16 + g) * PSTR;
                const int r1 = r0 + 8 * PSTR;
                uint32_t ahi[4], alo[4];
                ahi[0] = sAh[r0 + kb];     ahi[1] = sAh[r1 + kb];
                ahi[2] = sAh[r0 + kb + 4]; ahi[3] = sAh[r1 + kb + 4];
                alo[0] = sAl[r0 + kb];     alo[1] = sAl[r1 + kb];
                alo[2] = sAl[r0 + kb + 4]; alo[3] = sAl[r1 + kb + 4];
#pragma unroll
                for (int ni = 0; ni < 8; ni++) mma_bf16(acc[mi][ni], ahi, bhi[ni]);
#pragma unroll
                for (int ni = 0; ni < 8; ni++) mma_bf16(acc[mi][ni], alo, bhi[ni]);
#pragma unroll
                for (int ni = 0; ni < 8; ni++) mma_bf16(acc[mi][ni], ahi, blo[ni]);
            }
        }
    }

#pragma unroll
    for (int mi = 0; mi < 4; mi++) {
        const int r0 = bm + wm * 64 + mi * 16 + g;
#pragma unroll
        for (int ni = 0; ni < 8; ni++) {
            const int col = bn + wn * 64 + ni * 8 + q * 2;
            *(float2*)&C[(size_t)r0 * D_MODEL + col] =
                make_float2(acc[mi][ni][0], acc[mi][ni][1]);
            *(float2*)&C[(size_t)(r0 + 8) * D_MODEL + col] =
                make_float2(acc[mi][ni][2], acc[mi][ni][3]);
        }
    }
}

// ---------------------------------------------------------------------------
// Flash attention (causal), SIMT — unchanged from R7 (2 CTAs/SM).
// ---------------------------------------------------------------------------
#define QS_STRIDE 128
#define KS_STRIDE 128
#define VS_STRIDE 128
#define PS_STRIDE 65
#define SM_QS 0
#define SM_KS (SM_QS + 64 * QS_STRIDE)
#define SM_VS (SM_KS + 64 * KS_STRIDE)
#define SM_PS (SM_VS + 64 * VS_STRIDE)
#define ATT_SMEM_FLOATS (SM_PS + 64 * PS_STRIDE)
#define ATT_SMEM_BYTES  (ATT_SMEM_FLOATS * 4)      // 114944
#define NEG_BIG (-1.0e30f)

__global__ void __launch_bounds__(256, 2) attn_kernel(
    const float* __restrict__ Q, const float* __restrict__ K,
    const float* __restrict__ V, float* __restrict__ O)
{
    extern __shared__ float sm[];
    float* Qs = sm + SM_QS;
    float* Ks = sm + SM_KS;
    float* Vs = sm + SM_VS;
    float* Ps = sm + SM_PS;

    const int t  = threadIdx.x;
    const int w  = t >> 5;
    const int l  = t & 31;
    const int bh = blockIdx.y;
    const int b  = bh >> 4;
    const int h  = bh & 15;
    const int mt = blockIdx.x;
    const size_t base = ((size_t)b * SEQ) * D_MODEL + (size_t)h * DHEAD;
    const float scale = 0.088388347648318447f;

#pragma unroll
    for (int it = 0; it < 8; it++) {
        const int i  = it * 256 + t;
        const int r  = i >> 5;
        const int c4 = (i & 31);
        *(float4*)&Qs[r * QS_STRIDE + c4 * 4] =
            *(const float4*)(Q + base + (size_t)(mt * 64 + r) * D_MODEL + c4 * 4);
    }

    float m_i[8], l_i[8], acc[8][4];
#pragma unroll
    for (int i = 0; i < 8; i++) {
        m_i[i] = NEG_BIG; l_i[i] = 0.0f;
        acc[i][0] = acc[i][1] = acc[i][2] = acc[i][3] = 0.0f;
    }

    const int r0 = w * 8;

    for (int nt = 0; nt <= mt; nt++) {
        __syncthreads();
#pragma unroll
        for (int it = 0; it < 8; it++) {
            const int i  = it * 256 + t;
            const int r  = i >> 5;
            const int c4 = (i & 31);
            const size_t goff = base + (size_t)(nt * 64 + r) * D_MODEL + c4 * 4;
            *(float4*)&Ks[r * KS_STRIDE + ((c4 ^ (r & 31)) * 4)] =
                *(const float4*)(K + goff);
            *(float4*)&Vs[r * VS_STRIDE + c4 * 4] = *(const float4*)(V + goff);
        }
        __syncthreads();

        float s0[8], s1[8];
#pragma unroll
        for (int i = 0; i < 8; i++) { s0[i] = 0.0f; s1[i] = 0.0f; }
#pragma unroll 4
        for (int k4 = 0; k4 < 32; k4++) {
            const int sc = (k4 ^ l) * 4;
            const float4 kv0 = *(const float4*)&Ks[l * KS_STRIDE + sc];
            const float4 kv1 = *(const float4*)&Ks[(32 + l) * KS_STRIDE + sc];
            const int kk = k4 * 4;
#pragma unroll
            for (int i = 0; i < 8; i++) {
                const float4 qv = *(const float4*)&Qs[(r0 + i) * QS_STRIDE + kk];
                s0[i] += qv.x * kv0.x + qv.y * kv0.y + qv.z * kv0.z + qv.w * kv0.w;
                s1[i] += qv.x * kv1.x + qv.y * kv1.y + qv.z * kv1.z + qv.w * kv1.w;
            }
        }

        const bool diag = (nt == mt);
#pragma unroll
        for (int i = 0; i < 8; i++) {
            const int qg = mt * 64 + r0 + i;
            float sv0 = s0[i] * scale;
            float sv1 = s1[i] * scale;
            if (diag) {
                if (nt * 64 + l      > qg) sv0 = NEG_BIG;
                if (nt * 64 + 32 + l > qg) sv1 = NEG_BIG;
            }
            float mx = fmaxf(sv0, sv1);
#pragma unroll
            for (int off = 16; off > 0; off >>= 1)
                mx = fmaxf(mx, __shfl_xor_sync(0xffffffffu, mx, off));
            const float mnew  = fmaxf(m_i[i], mx);
            const float alpha = __expf(m_i[i] - mnew);
            const float p0 = __expf(sv0 - mnew);
            const float p1 = __expf(sv1 - mnew);
            float rs = p0 + p1;
#pragma unroll
            for (int off = 16; off > 0; off >>= 1)
                rs += __shfl_xor_sync(0xffffffffu, rs, off);
            l_i[i] = l_i[i] * alpha + rs;
            m_i[i] = mnew;
            acc[i][0] *= alpha; acc[i][1] *= alpha;
            acc[i][2] *= alpha; acc[i][3] *= alpha;
            Ps[(r0 + i) * PS_STRIDE + l]      = p0;
            Ps[(r0 + i) * PS_STRIDE + 32 + l] = p1;
        }
        __syncwarp();

#pragma unroll 4
        for (int c = 0; c < 64; c++) {
            const float4 vv = *(const float4*)&Vs[c * VS_STRIDE + l * 4];
#pragma unroll
            for (int i = 0; i < 8; i++) {
                const float p = Ps[(r0 + i) * PS_STRIDE + c];
                acc[i][0] += p * vv.x;
                acc[i][1] += p * vv.y;
                acc[i][2] += p * vv.z;
                acc[i][3] += p * vv.w;
            }
        }
        __syncwarp();
    }

#pragma unroll
    for (int i = 0; i < 8; i++) {
        const float inv = 1.0f / l_i[i];
        const int qg = mt * 64 + r0 + i;
        float4 o = make_float4(acc[i][0] * inv, acc[i][1] * inv,
                               acc[i][2] * inv, acc[i][3] * inv);
        *(float4*)(O + base + (size_t)qg * D_MODEL + l * 4) = o;
    }
}

// ---------------------------------------------------------------------------
// Launcher
// ---------------------------------------------------------------------------
extern "C" void kernel_launch(void* const* d_in, const int* in_sizes, int n_in,
                              void* d_out, int out_size)
{
    const float* x  = (const float*)d_in[0];
    const float* Wq = (const float*)d_in[1];
    const float* Wk = (const float*)d_in[2];
    const float* Wv = (const float*)d_in[3];
    const float* Wo = (const float*)d_in[4];
    float* out = (float*)d_out;

    void *pQ, *pK, *pV, *pA, *pXh, *pXl, *pWh, *pWl;
    cudaGetSymbolAddress(&pQ,  g_Q);
    cudaGetSymbolAddress(&pK,  g_K);
    cudaGetSymbolAddress(&pV,  g_V);
    cudaGetSymbolAddress(&pA,  g_AO);
    cudaGetSymbolAddress(&pXh, g_Xhi);
    cudaGetSymbolAddress(&pXl, g_Xlo);
    cudaGetSymbolAddress(&pWh, g_Whi);
    cudaGetSymbolAddress(&pWl, g_Wlo);

    uint32_t* Xh = (uint32_t*)pXh; uint32_t* Xl = (uint32_t*)pXl;
    uint32_t* Wh = (uint32_t*)pWh; uint32_t* Wl = (uint32_t*)pWl;

    cudaFuncSetAttribute(gemm_pre,
                         cudaFuncAttributeMaxDynamicSharedMemorySize, GEMM_SMEM_BYTES);
    cudaFuncSetAttribute(attn_kernel,
                         cudaFuncAttributeMaxDynamicSharedMemorySize, ATT_SMEM_BYTES);

    const int n2x = MROWS * D_MODEL / 2;     // 8388608
    const int n2w = D_MODEL * D_MODEL / 2;   // 2097152
    const dim3 ggrid(D_MODEL / GBN, MROWS / GBM);        // (8, 64)
    const dim3 attn_grid(SEQ / 64, BATCH * NHEADS);      // (32, 64)

    split_kernel<<<n2x / 256, 256>>>(x, Xh, Xl, n2x);

    split_kernel<<<n2w / 256, 256>>>(Wq, Wh, Wl, n2w);
    gemm_pre<<<ggrid, 256, GEMM_SMEM_BYTES>>>(Xh, Xl, Wh, Wl, (float*)pQ);

    split_kernel<<<n2w / 256, 256>>>(Wk, Wh, Wl, n2w);
    gemm_pre<<<ggrid, 256, GEMM_SMEM_BYTES>>>(Xh, Xl, Wh, Wl, (float*)pK);

    split_kernel<<<n2w / 256, 256>>>(Wv, Wh, Wl, n2w);
    gemm_pre<<<ggrid, 256, GEMM_SMEM_BYTES>>>(Xh, Xl, Wh, Wl, (float*)pV);

    attn_kernel<<<attn_grid, 256, ATT_SMEM_BYTES>>>(
        (const float*)pQ, (const float*)pK, (const float*)pV, (float*)pA);

    split_kernel<<<n2x / 256, 256>>>((const float*)pA, Xh, Xl, n2x);
    split_kernel<<<n2w / 256, 256>>>(Wo, Wh, Wl, n2w);
    gemm_pre<<<ggrid, 256, GEMM_SMEM_BYTES>>>(Xh, Xl, Wh, Wl, out);
}